// round 1
// baseline (speedup 1.0000x reference)
#include <cuda_runtime.h>
#include <math.h>

#define NR 13824
#define ND 1728
#define EDIM 512

// Scratch for projected features: [rows, 512] laid out as repr(256)|con(128)|off(128)
__device__ float g_rfeat[(size_t)NR * EDIM];
__device__ float g_dfeat[(size_t)ND * EDIM];

// ---------------------------------------------------------------------------
// Kernel 1: feats = (latents + positional) @ concat(Wp,Wc,Wo) + concat(bp,bc,bo)
// Tiled 64x64 GEMM, 256 threads, 4x4 micro-tile, K chunks of 16.
// blockIdx.y selects the 64-wide output column tile (0-3: proj, 4-5: con, 6-7: off)
// ---------------------------------------------------------------------------
__global__ __launch_bounds__(256) void proj_kernel(
    const float* __restrict__ lat, const float* __restrict__ pos,
    const float* __restrict__ Wp, const float* __restrict__ bp,
    const float* __restrict__ Wc, const float* __restrict__ bc,
    const float* __restrict__ Wo, const float* __restrict__ bo,
    float* __restrict__ outf)
{
    __shared__ float As[16][68];   // [k][row]
    __shared__ float Bs[16][68];   // [k][col]
    const int tid = threadIdx.x;
    const int ty = tid >> 4, tx = tid & 15;
    const int rowBase = blockIdx.x * 64;
    const int by = blockIdx.y;

    const float* W; const float* bias; int ld, colBase;
    if (by < 4)      { W = Wp; bias = bp; ld = 256; colBase = by * 64; }
    else if (by < 6) { W = Wc; bias = bc; ld = 128; colBase = (by - 4) * 64; }
    else             { W = Wo; bias = bo; ld = 128; colBase = (by - 6) * 64; }
    const int gcolBase = by * 64;

    const int ar  = tid >> 2;          // A-loader row 0..63
    const int aq  = (tid & 3) * 4;     // A-loader k offset
    const int bkr = tid >> 4;          // B-loader k row 0..15
    const int bcq = (tid & 15) * 4;    // B-loader col 0..60

    float acc[4][4] = {};

    for (int k0 = 0; k0 < EDIM; k0 += 16) {
        __syncthreads();
        float4 l4 = *(const float4*)(lat + (size_t)(rowBase + ar) * EDIM + k0 + aq);
        float4 p4 = *(const float4*)(pos + (size_t)(rowBase + ar) * EDIM + k0 + aq);
        As[aq + 0][ar] = l4.x + p4.x;
        As[aq + 1][ar] = l4.y + p4.y;
        As[aq + 2][ar] = l4.z + p4.z;
        As[aq + 3][ar] = l4.w + p4.w;
        float4 w4 = *(const float4*)(W + (size_t)(k0 + bkr) * ld + colBase + bcq);
        Bs[bkr][bcq + 0] = w4.x;
        Bs[bkr][bcq + 1] = w4.y;
        Bs[bkr][bcq + 2] = w4.z;
        Bs[bkr][bcq + 3] = w4.w;
        __syncthreads();
        #pragma unroll
        for (int kk = 0; kk < 16; kk++) {
            float4 a4 = *(const float4*)&As[kk][ty * 4];
            float4 b4 = *(const float4*)&Bs[kk][tx * 4];
            float a[4] = {a4.x, a4.y, a4.z, a4.w};
            float b[4] = {b4.x, b4.y, b4.z, b4.w};
            #pragma unroll
            for (int i = 0; i < 4; i++)
                #pragma unroll
                for (int j = 0; j < 4; j++)
                    acc[i][j] = fmaf(a[i], b[j], acc[i][j]);
        }
    }
    #pragma unroll
    for (int i = 0; i < 4; i++) {
        const int gr = rowBase + ty * 4 + i;
        #pragma unroll
        for (int j = 0; j < 4; j++) {
            const int c = tx * 4 + j;
            outf[(size_t)gr * EDIM + gcolBase + c] = acc[i][j] + bias[colBase + c];
        }
    }
}

// ---------------------------------------------------------------------------
// Kernel 2: fused flash-style attention.
// Per CTA: 64 range rows. Stream domain tiles of 64. For each tile:
//   - three 64x64 S tiles (K segments 256/128/128) via smem GEMM
//   - logits*0.25, contrast=tanh(.)*1.8, offset=tanh(.)
//   - online softmax (m,l); accumulate (p*contrast)@Vtile and sum(p*offset)
// Final: out = (accV + accO) / l
// ---------------------------------------------------------------------------
__global__ __launch_bounds__(256) void attn_kernel(
    const float* __restrict__ rfeat, const float* __restrict__ dfeat,
    const float* __restrict__ dflat, float* __restrict__ out)
{
    __shared__ float As[16][68];   // [k][range row]
    __shared__ float Bs[16][68];   // [k][domain row]
    __shared__ float Ps[64][68];   // p * contrast, [range row][domain]
    __shared__ float Vs[64][68];   // domain_flat tile, [domain][64]

    const int tid = threadIdx.x;
    const int ty = tid >> 4, tx = tid & 15;
    const int rowBase = blockIdx.x * 64;
    const int ar = tid >> 2;
    const int aq = (tid & 3) * 4;
    const int vrow = tid >> 2;            // V-loader row
    const int vcq  = (tid & 3) * 16;      // V-loader col base

    float m_i[4], l_i[4], accO[4], C[4][4];
    #pragma unroll
    for (int i = 0; i < 4; i++) {
        m_i[i] = -1e30f; l_i[i] = 0.f; accO[i] = 0.f;
        #pragma unroll
        for (int j = 0; j < 4; j++) C[i][j] = 0.f;
    }

    const float inv_sqrt_h = 0.08838834764831845f;  // 1/sqrt(128)
    const float lscale = 0.25f;                     // 1/(sqrt(256)*0.25)

    #define K_GEMM(K0, K1, ACC)                                                        \
        for (int k0 = (K0); k0 < (K1); k0 += 16) {                                     \
            __syncthreads();                                                           \
            { float4 a4 = *(const float4*)(rfeat + (size_t)(rowBase + ar) * EDIM + k0 + aq); \
              As[aq+0][ar] = a4.x; As[aq+1][ar] = a4.y;                                \
              As[aq+2][ar] = a4.z; As[aq+3][ar] = a4.w;                                \
              float4 b4 = *(const float4*)(dfeat + (size_t)(d0 + ar) * EDIM + k0 + aq); \
              Bs[aq+0][ar] = b4.x; Bs[aq+1][ar] = b4.y;                                \
              Bs[aq+2][ar] = b4.z; Bs[aq+3][ar] = b4.w; }                              \
            __syncthreads();                                                           \
            _Pragma("unroll")                                                          \
            for (int kk = 0; kk < 16; kk++) {                                          \
                float4 a4 = *(const float4*)&As[kk][ty * 4];                           \
                float4 b4 = *(const float4*)&Bs[kk][tx * 4];                           \
                float a_[4] = {a4.x, a4.y, a4.z, a4.w};                                \
                float b_[4] = {b4.x, b4.y, b4.z, b4.w};                                \
                _Pragma("unroll") for (int i_ = 0; i_ < 4; i_++)                       \
                _Pragma("unroll") for (int j_ = 0; j_ < 4; j_++)                       \
                    ACC[i_][j_] = fmaf(a_[i_], b_[j_], ACC[i_][j_]);                   \
            }                                                                          \
        }

    for (int d0 = 0; d0 < ND; d0 += 64) {
        float Sr[4][4] = {}, Sc[4][4] = {}, So[4][4] = {};
        K_GEMM(0,   256, Sr)   // logits segment (repr)
        K_GEMM(256, 384, Sc)   // contrast segment (con)
        K_GEMM(384, 512, So)   // offset segment (off)

        // transforms + row max
        float Cn[4][4], On[4][4], rmax[4];
        #pragma unroll
        for (int i = 0; i < 4; i++) {
            rmax[i] = -1e30f;
            #pragma unroll
            for (int j = 0; j < 4; j++) {
                float lg = Sr[i][j] * lscale;
                Sr[i][j] = lg;
                rmax[i] = fmaxf(rmax[i], lg);
                Cn[i][j] = tanhf(Sc[i][j] * inv_sqrt_h) * 1.8f;
                On[i][j] = tanhf(So[i][j] * inv_sqrt_h);
            }
        }
        // row-max across the 16 tx lanes (stays within half-warp)
        #pragma unroll
        for (int i = 0; i < 4; i++) {
            #pragma unroll
            for (int off = 8; off >= 1; off >>= 1)
                rmax[i] = fmaxf(rmax[i], __shfl_xor_sync(0xffffffffu, rmax[i], off));
        }

        // online softmax update + stage p*contrast into Ps
        #pragma unroll
        for (int i = 0; i < 4; i++) {
            float mnew = fmaxf(m_i[i], rmax[i]);
            float factor = __expf(m_i[i] - mnew);
            m_i[i] = mnew;
            l_i[i] *= factor;
            accO[i] *= factor;
            #pragma unroll
            for (int j = 0; j < 4; j++) C[i][j] *= factor;
            #pragma unroll
            for (int j = 0; j < 4; j++) {
                float p = __expf(Sr[i][j] - mnew);
                l_i[i] += p;
                accO[i] = fmaf(p, On[i][j], accO[i]);
                Ps[ty * 4 + i][tx * 4 + j] = p * Cn[i][j];
            }
        }

        // load V tile (domain_flat [64 dom][64])
        #pragma unroll
        for (int q = 0; q < 4; q++) {
            float4 v4 = *(const float4*)(dflat + (size_t)(d0 + vrow) * 64 + vcq + q * 4);
            *(float4*)&Vs[vrow][vcq + q * 4] = v4;
        }
        __syncthreads();

        // PV GEMM: C += Ps[rows][d] * Vs[d][cols]
        #pragma unroll 8
        for (int d = 0; d < 64; d++) {
            float4 v4 = *(const float4*)&Vs[d][tx * 4];
            float vj[4] = {v4.x, v4.y, v4.z, v4.w};
            float pr[4];
            #pragma unroll
            for (int i = 0; i < 4; i++) pr[i] = Ps[ty * 4 + i][d];
            #pragma unroll
            for (int i = 0; i < 4; i++)
                #pragma unroll
                for (int j = 0; j < 4; j++)
                    C[i][j] = fmaf(pr[i], vj[j], C[i][j]);
        }
        // next iteration's first __syncthreads() protects Ps/Vs reuse
    }
    #undef K_GEMM

    // final cross-lane reduction of l and accO, normalize, store
    #pragma unroll
    for (int i = 0; i < 4; i++) {
        #pragma unroll
        for (int off = 8; off >= 1; off >>= 1) {
            l_i[i]  += __shfl_xor_sync(0xffffffffu, l_i[i], off);
            accO[i] += __shfl_xor_sync(0xffffffffu, accO[i], off);
        }
        float inv = 1.0f / l_i[i];
        float4 o4;
        o4.x = (C[i][0] + accO[i]) * inv;
        o4.y = (C[i][1] + accO[i]) * inv;
        o4.z = (C[i][2] + accO[i]) * inv;
        o4.w = (C[i][3] + accO[i]) * inv;
        *(float4*)(out + (size_t)(rowBase + ty * 4 + i) * 64 + tx * 4) = o4;
    }
}

extern "C" void kernel_launch(void* const* d_in, const int* in_sizes, int n_in,
                              void* d_out, int out_size)
{
    const float* pooled  = (const float*)d_in[0];
    const float* rlat    = (const float*)d_in[1];
    const float* dlat    = (const float*)d_in[2];
    const float* rpos    = (const float*)d_in[3];
    const float* dpos    = (const float*)d_in[4];
    const float* W_rproj = (const float*)d_in[5];
    const float* b_rproj = (const float*)d_in[6];
    const float* W_dproj = (const float*)d_in[7];
    const float* b_dproj = (const float*)d_in[8];
    const float* W_rcon  = (const float*)d_in[9];
    const float* b_rcon  = (const float*)d_in[10];
    const float* W_dcon  = (const float*)d_in[11];
    const float* b_dcon  = (const float*)d_in[12];
    const float* W_roff  = (const float*)d_in[13];
    const float* b_roff  = (const float*)d_in[14];
    const float* W_doff  = (const float*)d_in[15];
    const float* b_doff  = (const float*)d_in[16];
    float* out = (float*)d_out;

    float* rfeat; float* dfeat;
    cudaGetSymbolAddress((void**)&rfeat, g_rfeat);
    cudaGetSymbolAddress((void**)&dfeat, g_dfeat);

    proj_kernel<<<dim3(NR / 64, 8), 256>>>(rlat, rpos, W_rproj, b_rproj,
                                           W_rcon, b_rcon, W_roff, b_roff, rfeat);
    proj_kernel<<<dim3(ND / 64, 8), 256>>>(dlat, dpos, W_dproj, b_dproj,
                                           W_dcon, b_dcon, W_doff, b_doff, dfeat);
    attn_kernel<<<NR / 64, 256>>>(rfeat, dfeat, pooled, out);
}

// round 2
// speedup vs baseline: 1.0013x; 1.0013x over previous
#include <cuda_runtime.h>
#include <math.h>

#define NR 13824
#define ND 1728
#define EDIM 512

// Scratch for projected features: [rows, 512] laid out as repr(256)|con(128)|off(128)
__device__ float g_rfeat[(size_t)NR * EDIM];
__device__ float g_dfeat[(size_t)ND * EDIM];

// ---------------------------------------------------------------------------
// Kernel 1: feats = (latents + positional) @ concat(Wp,Wc,Wo) + concat(bp,bc,bo)
// Tiled 64x64 GEMM, 256 threads, 4x4 micro-tile, K chunks of 16.
// blockIdx.y selects the 64-wide output column tile (0-3: proj, 4-5: con, 6-7: off)
// ---------------------------------------------------------------------------
__global__ __launch_bounds__(256) void proj_kernel(
    const float* __restrict__ lat, const float* __restrict__ pos,
    const float* __restrict__ Wp, const float* __restrict__ bp,
    const float* __restrict__ Wc, const float* __restrict__ bc,
    const float* __restrict__ Wo, const float* __restrict__ bo,
    float* __restrict__ outf)
{
    __shared__ float As[16][68];   // [k][row]
    __shared__ float Bs[16][68];   // [k][col]
    const int tid = threadIdx.x;
    const int ty = tid >> 4, tx = tid & 15;
    const int rowBase = blockIdx.x * 64;
    const int by = blockIdx.y;

    const float* W; const float* bias; int ld, colBase;
    if (by < 4)      { W = Wp; bias = bp; ld = 256; colBase = by * 64; }
    else if (by < 6) { W = Wc; bias = bc; ld = 128; colBase = (by - 4) * 64; }
    else             { W = Wo; bias = bo; ld = 128; colBase = (by - 6) * 64; }
    const int gcolBase = by * 64;

    const int ar  = tid >> 2;          // A-loader row 0..63
    const int aq  = (tid & 3) * 4;     // A-loader k offset
    const int bkr = tid >> 4;          // B-loader k row 0..15
    const int bcq = (tid & 15) * 4;    // B-loader col 0..60

    float acc[4][4] = {};

    for (int k0 = 0; k0 < EDIM; k0 += 16) {
        __syncthreads();
        float4 l4 = *(const float4*)(lat + (size_t)(rowBase + ar) * EDIM + k0 + aq);
        float4 p4 = *(const float4*)(pos + (size_t)(rowBase + ar) * EDIM + k0 + aq);
        As[aq + 0][ar] = l4.x + p4.x;
        As[aq + 1][ar] = l4.y + p4.y;
        As[aq + 2][ar] = l4.z + p4.z;
        As[aq + 3][ar] = l4.w + p4.w;
        float4 w4 = *(const float4*)(W + (size_t)(k0 + bkr) * ld + colBase + bcq);
        Bs[bkr][bcq + 0] = w4.x;
        Bs[bkr][bcq + 1] = w4.y;
        Bs[bkr][bcq + 2] = w4.z;
        Bs[bkr][bcq + 3] = w4.w;
        __syncthreads();
        #pragma unroll
        for (int kk = 0; kk < 16; kk++) {
            float4 a4 = *(const float4*)&As[kk][ty * 4];
            float4 b4 = *(const float4*)&Bs[kk][tx * 4];
            float a[4] = {a4.x, a4.y, a4.z, a4.w};
            float b[4] = {b4.x, b4.y, b4.z, b4.w};
            #pragma unroll
            for (int i = 0; i < 4; i++)
                #pragma unroll
                for (int j = 0; j < 4; j++)
                    acc[i][j] = fmaf(a[i], b[j], acc[i][j]);
        }
    }
    #pragma unroll
    for (int i = 0; i < 4; i++) {
        const int gr = rowBase + ty * 4 + i;
        #pragma unroll
        for (int j = 0; j < 4; j++) {
            const int c = tx * 4 + j;
            outf[(size_t)gr * EDIM + gcolBase + c] = acc[i][j] + bias[colBase + c];
        }
    }
}

// ---------------------------------------------------------------------------
// Kernel 2: fused flash-style attention.
// Per CTA: 64 range rows. Stream domain tiles of 64. For each tile:
//   - three 64x64 S tiles (K segments 256/128/128) via smem GEMM
//   - logits*0.25, contrast=tanh(.)*1.8, offset=tanh(.)
//   - online softmax (m,l); accumulate (p*contrast)@Vtile and sum(p*offset)
// Final: out = (accV + accO) / l
// ---------------------------------------------------------------------------
__global__ __launch_bounds__(256) void attn_kernel(
    const float* __restrict__ rfeat, const float* __restrict__ dfeat,
    const float* __restrict__ dflat, float* __restrict__ out)
{
    __shared__ float As[16][68];   // [k][range row]
    __shared__ float Bs[16][68];   // [k][domain row]
    __shared__ float Ps[64][68];   // p * contrast, [range row][domain]
    __shared__ float Vs[64][68];   // domain_flat tile, [domain][64]

    const int tid = threadIdx.x;
    const int ty = tid >> 4, tx = tid & 15;
    const int rowBase = blockIdx.x * 64;
    const int ar = tid >> 2;
    const int aq = (tid & 3) * 4;
    const int vrow = tid >> 2;            // V-loader row
    const int vcq  = (tid & 3) * 16;      // V-loader col base

    float m_i[4], l_i[4], accO[4], C[4][4];
    #pragma unroll
    for (int i = 0; i < 4; i++) {
        m_i[i] = -1e30f; l_i[i] = 0.f; accO[i] = 0.f;
        #pragma unroll
        for (int j = 0; j < 4; j++) C[i][j] = 0.f;
    }

    const float inv_sqrt_h = 0.08838834764831845f;  // 1/sqrt(128)
    const float lscale = 0.25f;                     // 1/(sqrt(256)*0.25)

    #define K_GEMM(K0, K1, ACC)                                                        \
        for (int k0 = (K0); k0 < (K1); k0 += 16) {                                     \
            __syncthreads();                                                           \
            { float4 a4 = *(const float4*)(rfeat + (size_t)(rowBase + ar) * EDIM + k0 + aq); \
              As[aq+0][ar] = a4.x; As[aq+1][ar] = a4.y;                                \
              As[aq+2][ar] = a4.z; As[aq+3][ar] = a4.w;                                \
              float4 b4 = *(const float4*)(dfeat + (size_t)(d0 + ar) * EDIM + k0 + aq); \
              Bs[aq+0][ar] = b4.x; Bs[aq+1][ar] = b4.y;                                \
              Bs[aq+2][ar] = b4.z; Bs[aq+3][ar] = b4.w; }                              \
            __syncthreads();                                                           \
            _Pragma("unroll")                                                          \
            for (int kk = 0; kk < 16; kk++) {                                          \
                float4 a4 = *(const float4*)&As[kk][ty * 4];                           \
                float4 b4 = *(const float4*)&Bs[kk][tx * 4];                           \
                float a_[4] = {a4.x, a4.y, a4.z, a4.w};                                \
                float b_[4] = {b4.x, b4.y, b4.z, b4.w};                                \
                _Pragma("unroll") for (int i_ = 0; i_ < 4; i_++)                       \
                _Pragma("unroll") for (int j_ = 0; j_ < 4; j_++)                       \
                    ACC[i_][j_] = fmaf(a_[i_], b_[j_], ACC[i_][j_]);                   \
            }                                                                          \
        }

    for (int d0 = 0; d0 < ND; d0 += 64) {
        float Sr[4][4] = {}, Sc[4][4] = {}, So[4][4] = {};
        K_GEMM(0,   256, Sr)   // logits segment (repr)
        K_GEMM(256, 384, Sc)   // contrast segment (con)
        K_GEMM(384, 512, So)   // offset segment (off)

        // transforms + row max
        float Cn[4][4], On[4][4], rmax[4];
        #pragma unroll
        for (int i = 0; i < 4; i++) {
            rmax[i] = -1e30f;
            #pragma unroll
            for (int j = 0; j < 4; j++) {
                float lg = Sr[i][j] * lscale;
                Sr[i][j] = lg;
                rmax[i] = fmaxf(rmax[i], lg);
                Cn[i][j] = tanhf(Sc[i][j] * inv_sqrt_h) * 1.8f;
                On[i][j] = tanhf(So[i][j] * inv_sqrt_h);
            }
        }
        // row-max across the 16 tx lanes (stays within half-warp)
        #pragma unroll
        for (int i = 0; i < 4; i++) {
            #pragma unroll
            for (int off = 8; off >= 1; off >>= 1)
                rmax[i] = fmaxf(rmax[i], __shfl_xor_sync(0xffffffffu, rmax[i], off));
        }

        // online softmax update + stage p*contrast into Ps
        #pragma unroll
        for (int i = 0; i < 4; i++) {
            float mnew = fmaxf(m_i[i], rmax[i]);
            float factor = __expf(m_i[i] - mnew);
            m_i[i] = mnew;
            l_i[i] *= factor;
            accO[i] *= factor;
            #pragma unroll
            for (int j = 0; j < 4; j++) C[i][j] *= factor;
            #pragma unroll
            for (int j = 0; j < 4; j++) {
                float p = __expf(Sr[i][j] - mnew);
                l_i[i] += p;
                accO[i] = fmaf(p, On[i][j], accO[i]);
                Ps[ty * 4 + i][tx * 4 + j] = p * Cn[i][j];
            }
        }

        // load V tile (domain_flat [64 dom][64])
        #pragma unroll
        for (int q = 0; q < 4; q++) {
            float4 v4 = *(const float4*)(dflat + (size_t)(d0 + vrow) * 64 + vcq + q * 4);
            *(float4*)&Vs[vrow][vcq + q * 4] = v4;
        }
        __syncthreads();

        // PV GEMM: C += Ps[rows][d] * Vs[d][cols]
        #pragma unroll 8
        for (int d = 0; d < 64; d++) {
            float4 v4 = *(const float4*)&Vs[d][tx * 4];
            float vj[4] = {v4.x, v4.y, v4.z, v4.w};
            float pr[4];
            #pragma unroll
            for (int i = 0; i < 4; i++) pr[i] = Ps[ty * 4 + i][d];
            #pragma unroll
            for (int i = 0; i < 4; i++)
                #pragma unroll
                for (int j = 0; j < 4; j++)
                    C[i][j] = fmaf(pr[i], vj[j], C[i][j]);
        }
        // next iteration's first __syncthreads() protects Ps/Vs reuse
    }
    #undef K_GEMM

    // final cross-lane reduction of l and accO, normalize, store
    #pragma unroll
    for (int i = 0; i < 4; i++) {
        #pragma unroll
        for (int off = 8; off >= 1; off >>= 1) {
            l_i[i]  += __shfl_xor_sync(0xffffffffu, l_i[i], off);
            accO[i] += __shfl_xor_sync(0xffffffffu, accO[i], off);
        }
        float inv = 1.0f / l_i[i];
        float4 o4;
        o4.x = (C[i][0] + accO[i]) * inv;
        o4.y = (C[i][1] + accO[i]) * inv;
        o4.z = (C[i][2] + accO[i]) * inv;
        o4.w = (C[i][3] + accO[i]) * inv;
        *(float4*)(out + (size_t)(rowBase + ty * 4 + i) * 64 + tx * 4) = o4;
    }
}

extern "C" void kernel_launch(void* const* d_in, const int* in_sizes, int n_in,
                              void* d_out, int out_size)
{
    const float* pooled  = (const float*)d_in[0];
    const float* rlat    = (const float*)d_in[1];
    const float* dlat    = (const float*)d_in[2];
    const float* rpos    = (const float*)d_in[3];
    const float* dpos    = (const float*)d_in[4];
    const float* W_rproj = (const float*)d_in[5];
    const float* b_rproj = (const float*)d_in[6];
    const float* W_dproj = (const float*)d_in[7];
    const float* b_dproj = (const float*)d_in[8];
    const float* W_rcon  = (const float*)d_in[9];
    const float* b_rcon  = (const float*)d_in[10];
    const float* W_dcon  = (const float*)d_in[11];
    const float* b_dcon  = (const float*)d_in[12];
    const float* W_roff  = (const float*)d_in[13];
    const float* b_roff  = (const float*)d_in[14];
    const float* W_doff  = (const float*)d_in[15];
    const float* b_doff  = (const float*)d_in[16];
    float* out = (float*)d_out;

    float* rfeat; float* dfeat;
    cudaGetSymbolAddress((void**)&rfeat, g_rfeat);
    cudaGetSymbolAddress((void**)&dfeat, g_dfeat);

    proj_kernel<<<dim3(NR / 64, 8), 256>>>(rlat, rpos, W_rproj, b_rproj,
                                           W_rcon, b_rcon, W_roff, b_roff, rfeat);
    proj_kernel<<<dim3(ND / 64, 8), 256>>>(dlat, dpos, W_dproj, b_dproj,
                                           W_dcon, b_dcon, W_doff, b_doff, dfeat);
    attn_kernel<<<NR / 64, 256>>>(rfeat, dfeat, pooled, out);
}